// round 1
// baseline (speedup 1.0000x reference)
#include <cuda_runtime.h>
#include <cuda_fp16.h>
#include <cstdint>

// GhostLinearTandem: out[512,8192] = x[512,4096] @ W^T,
//   W[o,i] = lut[base_idx[o,i]*256 + fine_idx[o,i]] * scale[o]
//
// Strategy:
//  - prepass: round x to tf32 (rna) into __device__ scratch; lut -> fp16 copy
//  - main: tiled tf32 mma.sync GEMM, BM=128 BN=128 BK=32, fused dequant:
//    idx int4 LDG (prefetched 1 stage ahead) -> smem fp16 LUT gather -> *scale
//    -> cvt.rna.tf32 -> STS. cp.async double-buffered x tiles.
//  - grid (M-fastest) so the 4 M-blocks per N-tile share idx reads in L2.

#define M_TOTAL 512
#define N_TOTAL 8192
#define K_TOTAL 4096
#define BM 128
#define BN 128
#define BK 32
#define LDT 36            // BK + 4 pad (floats) -> conflict-free frag LDS
#define THREADS 256
#define NSTAGES (K_TOTAL / BK)   // 128
#define LUT_BYTES 131072         // 65536 * fp16
#define TILE_U32 (BM * LDT)      // 4608 words per buffer
#define SMEM_BYTES (LUT_BYTES + 4 * TILE_U32 * 4)  // 131072 + 73728 = 204800

__device__ float  g_xr[M_TOTAL * K_TOTAL];   // tf32-rounded x (8 MB scratch)
__device__ __half g_lut_h[65536];            // fp16 LUT (128 KB)

__device__ __forceinline__ uint32_t f2tf32(float f) {
    uint32_t r;
    asm("cvt.rna.tf32.f32 %0, %1;" : "=r"(r) : "f"(f));
    return r;
}

#define CP16(dst_u32, src_ptr) \
    asm volatile("cp.async.cg.shared.global [%0], [%1], 16;" :: "r"(dst_u32), "l"(src_ptr))
#define CP_COMMIT()  asm volatile("cp.async.commit_group;")
#define CP_WAIT0()   asm volatile("cp.async.wait_group 0;")

#define MMA_TF32(d, a, b)                                              \
    asm volatile(                                                      \
        "mma.sync.aligned.m16n8k8.row.col.f32.tf32.tf32.f32 "          \
        "{%0,%1,%2,%3}, {%4,%5,%6,%7}, {%8,%9}, {%0,%1,%2,%3};\n"      \
        : "+f"((d)[0]), "+f"((d)[1]), "+f"((d)[2]), "+f"((d)[3])       \
        : "r"((a)[0]), "r"((a)[1]), "r"((a)[2]), "r"((a)[3]),          \
          "r"((b)[0]), "r"((b)[1]))

__global__ void ghost_prepass(const float* __restrict__ x,
                              const float* __restrict__ lut) {
    int i = blockIdx.x * blockDim.x + threadIdx.x;
    int stride = gridDim.x * blockDim.x;
    for (int j = i; j < M_TOTAL * K_TOTAL; j += stride)
        g_xr[j] = __uint_as_float(f2tf32(x[j]));
    for (int j = i; j < 65536; j += stride)
        g_lut_h[j] = __float2half_rn(lut[j]);
}

__global__ __launch_bounds__(THREADS, 1)
void ghost_gemm(const int* __restrict__ base_idx,
                const int* __restrict__ fine_idx,
                const float* __restrict__ scale,
                float* __restrict__ out) {
    extern __shared__ char smem_raw[];
    __half*   lut_s = (__half*)smem_raw;
    uint32_t* As    = (uint32_t*)(smem_raw + LUT_BYTES);                    // 2 buffers
    uint32_t* Ws    = (uint32_t*)(smem_raw + LUT_BYTES + 2 * TILE_U32 * 4); // 2 buffers

    const int tid = threadIdx.x;
    const int m0 = blockIdx.x * BM;   // M fastest-varying -> L2 idx reuse
    const int n0 = blockIdx.y * BN;

    // ---- LUT -> smem (vectorized 16B) ----
    {
        const uint4* src = (const uint4*)g_lut_h;  // 8192 uint4
        uint4* dst = (uint4*)lut_s;
        #pragma unroll 4
        for (int i = tid; i < 8192; i += THREADS) dst[i] = src[i];
    }

    // ---- loader roles: thread t owns (row = t/2, 16-col half = t%2) ----
    const int lrow  = tid >> 1;         // 0..127
    const int lhalf = (tid & 1) * 16;   // 0 or 16
    const float scl = scale[n0 + lrow];
    const int4* bp = (const int4*)(base_idx + (size_t)(n0 + lrow) * K_TOTAL);
    const int4* fp = (const int4*)(fine_idx + (size_t)(n0 + lrow) * K_TOTAL);
    const float* xp = g_xr + (size_t)(m0 + lrow) * K_TOTAL;

    // ---- warp / fragment coords ----
    const int warp = tid >> 5, lane = tid & 31;
    const int warp_m = warp & 1;        // 2 warps along M (64 rows each)
    const int warp_n = warp >> 1;       // 4 warps along N (32 cols each)
    const int qid = lane >> 2, tg = lane & 3;

    float acc[4][4][4];
    #pragma unroll
    for (int mt = 0; mt < 4; mt++)
        #pragma unroll
        for (int nt = 0; nt < 4; nt++)
            #pragma unroll
            for (int r = 0; r < 4; r++) acc[mt][nt][r] = 0.0f;

    // ---- prologue: stage 0 prefetch ----
    int4 rb[4], rf[4];
    {
        int off = lhalf >> 2;   // stage 0, int4 units
        #pragma unroll
        for (int j = 0; j < 4; j++) { rb[j] = bp[off + j]; rf[j] = fp[off + j]; }
        uint32_t dst = (uint32_t)__cvta_generic_to_shared(&As[lrow * LDT + lhalf]);
        const float* sp = xp + lhalf;
        #pragma unroll
        for (int j = 0; j < 4; j++) CP16(dst + 16u * j, sp + 4 * j);
        CP_COMMIT();
    }
    __syncthreads();   // lut_s visible to all before first dequant gather

    int buf = 0;
    for (int s = 0; s < NSTAGES; ++s) {
        // ---- dequant prefetched indices -> Ws[buf] ----
        {
            uint32_t* wdst = &Ws[buf * TILE_U32 + lrow * LDT + lhalf];
            #pragma unroll
            for (int j = 0; j < 4; j++) {
                int4 b = rb[j], f = rf[j];
                uint4 pk;
                pk.x = f2tf32(__half2float(lut_s[(b.x << 8) + f.x]) * scl);
                pk.y = f2tf32(__half2float(lut_s[(b.y << 8) + f.y]) * scl);
                pk.z = f2tf32(__half2float(lut_s[(b.z << 8) + f.z]) * scl);
                pk.w = f2tf32(__half2float(lut_s[(b.w << 8) + f.w]) * scl);
                *(uint4*)(wdst + j * 4) = pk;
            }
        }
        CP_WAIT0();
        __syncthreads();   // As[buf] (x) + Ws[buf] (W) published

        // ---- prefetch stage s+1 ----
        if (s + 1 < NSTAGES) {
            int off = ((s + 1) * BK + lhalf) >> 2;
            #pragma unroll
            for (int j = 0; j < 4; j++) { rb[j] = bp[off + j]; rf[j] = fp[off + j]; }
            uint32_t dst = (uint32_t)__cvta_generic_to_shared(
                &As[(buf ^ 1) * TILE_U32 + lrow * LDT + lhalf]);
            const float* sp = xp + (s + 1) * BK + lhalf;
            #pragma unroll
            for (int j = 0; j < 4; j++) CP16(dst + 16u * j, sp + 4 * j);
            CP_COMMIT();
        }

        // ---- MMA over this tile ----
        {
            const uint32_t* A = &As[buf * TILE_U32];
            const uint32_t* W = &Ws[buf * TILE_U32];
            #pragma unroll
            for (int ks = 0; ks < 4; ks++) {
                const int kc = ks * 8 + tg;
                uint32_t afr[4][4], bfr[4][2];
                #pragma unroll
                for (int mt = 0; mt < 4; mt++) {
                    int r = warp_m * 64 + mt * 16 + qid;
                    afr[mt][0] = A[r * LDT + kc];
                    afr[mt][1] = A[(r + 8) * LDT + kc];
                    afr[mt][2] = A[r * LDT + kc + 4];
                    afr[mt][3] = A[(r + 8) * LDT + kc + 4];
                }
                #pragma unroll
                for (int nt = 0; nt < 4; nt++) {
                    int c = warp_n * 32 + nt * 8 + qid;
                    bfr[nt][0] = W[c * LDT + kc];
                    bfr[nt][1] = W[c * LDT + kc + 4];
                }
                #pragma unroll
                for (int mt = 0; mt < 4; mt++)
                    #pragma unroll
                    for (int nt = 0; nt < 4; nt++)
                        MMA_TF32(acc[mt][nt], afr[mt], bfr[nt]);
            }
        }
        __syncthreads();   // MMA(buf) done before next cp.async overwrites As[buf^1]... and 2-stage reuse of Ws
        buf ^= 1;
    }

    // ---- epilogue: write fp32 output ----
    #pragma unroll
    for (int mt = 0; mt < 4; mt++) {
        #pragma unroll
        for (int nt = 0; nt < 4; nt++) {
            int row = m0 + warp_m * 64 + mt * 16 + qid;
            int col = n0 + warp_n * 32 + nt * 8 + tg * 2;
            float2 v0 = make_float2(acc[mt][nt][0], acc[mt][nt][1]);
            float2 v1 = make_float2(acc[mt][nt][2], acc[mt][nt][3]);
            *(float2*)&out[(size_t)row * N_TOTAL + col] = v0;
            *(float2*)&out[(size_t)(row + 8) * N_TOTAL + col] = v1;
        }
    }
}

extern "C" void kernel_launch(void* const* d_in, const int* in_sizes, int n_in,
                              void* d_out, int out_size) {
    const float* x        = (const float*)d_in[0];
    const int*   base_idx = (const int*)d_in[1];
    const int*   fine_idx = (const int*)d_in[2];
    const float* scale    = (const float*)d_in[3];
    const float* lut      = (const float*)d_in[4];
    float* out = (float*)d_out;

    cudaFuncSetAttribute(ghost_gemm, cudaFuncAttributeMaxDynamicSharedMemorySize,
                         SMEM_BYTES);

    ghost_prepass<<<512, 256>>>(x, lut);
    dim3 grid(M_TOTAL / BM, N_TOTAL / BN);   // (4, 64), M fastest
    ghost_gemm<<<grid, THREADS, SMEM_BYTES>>>(base_idx, fine_idx, scale, out);
}

// round 3
// speedup vs baseline: 1.7007x; 1.7007x over previous
#include <cuda_runtime.h>
#include <cuda_fp16.h>
#include <cstdint>

// GhostLinearTandem, two-pass:
//  pass 1 (ghost_dequant): W[n,k] = fp16(lut[base*256+fine] * scale[n]) into
//    64MiB __device__ scratch. LUT fp16 in smem (128KB, 1 CTA/SM, 32 warps),
//    coalesced int4 index reads, 16B stores. DRAM-bound ~320MB.
//  pass 2 (ghost_gemm): out[512,8192] = x @ W^T, fp16 mma.sync m16n8k16,
//    BM=BN=128 BK=32, smem row stride 40 halves (conflict-free LDS+STS),
//    cp.async W tiles, reg-prefetched x with fp32->fp16 convert. 40KB smem
//    -> 2 CTAs/SM. Grid M-fastest for W L2 reuse.

#define M_TOTAL 512
#define N_TOTAL 8192
#define K_TOTAL 4096

__device__ __align__(16) __half g_W[(size_t)N_TOTAL * K_TOTAL];  // 64 MiB scratch

__device__ __forceinline__ uint32_t h2_to_u32(__half2 h) {
    uint32_t u;
    *(__half2*)&u = h;
    return u;
}

// ---------------------------------------------------------------- pass 1
__global__ __launch_bounds__(1024)
void ghost_dequant(const int* __restrict__ base_idx,
                   const int* __restrict__ fine_idx,
                   const float* __restrict__ scale,
                   const float* __restrict__ lut) {
    extern __shared__ __half lut_s[];  // 65536 fp16 = 128KB
    #pragma unroll 4
    for (int i = threadIdx.x; i < 65536; i += 1024)
        lut_s[i] = __float2half_rn(lut[i]);
    __syncthreads();

    const int4* bp = (const int4*)base_idx;
    const int4* fp = (const int4*)fine_idx;
    const size_t ngroups = (size_t)N_TOTAL * K_TOTAL / 8;  // 8 elems per group
    size_t t = (size_t)blockIdx.x * blockDim.x + threadIdx.x;
    size_t stride = (size_t)gridDim.x * blockDim.x;

    for (size_t g = t; g < ngroups; g += stride) {
        int row = (int)(g >> 9);              // 512 groups per row of 4096
        float scl = __ldg(&scale[row]);
        int4 b0 = bp[2 * g], b1 = bp[2 * g + 1];
        int4 f0 = fp[2 * g], f1 = fp[2 * g + 1];
        __half2 h[4];
        h[0] = __floats2half2_rn(__half2float(lut_s[(b0.x << 8) + f0.x]) * scl,
                                 __half2float(lut_s[(b0.y << 8) + f0.y]) * scl);
        h[1] = __floats2half2_rn(__half2float(lut_s[(b0.z << 8) + f0.z]) * scl,
                                 __half2float(lut_s[(b0.w << 8) + f0.w]) * scl);
        h[2] = __floats2half2_rn(__half2float(lut_s[(b1.x << 8) + f1.x]) * scl,
                                 __half2float(lut_s[(b1.y << 8) + f1.y]) * scl);
        h[3] = __floats2half2_rn(__half2float(lut_s[(b1.z << 8) + f1.z]) * scl,
                                 __half2float(lut_s[(b1.w << 8) + f1.w]) * scl);
        *(uint4*)&g_W[g * 8] = *(uint4*)h;
    }
}

// ---------------------------------------------------------------- pass 2
#define BM 128
#define BN 128
#define BK 32                 // halves per k-stage
#define LDH 40                // halves per smem row (8 pad)
#define LD32 20               // u32 per smem row
#define NS (K_TOTAL / BK)     // 128 stages
#define THREADS 256
#define TILE32 (128 * LD32)   // 2560 u32 per tile buffer
#define SMEM_GEMM (4 * TILE32 * 4)  // A0,A1,B0,B1 = 40960 bytes

#define CP16(dst_u32, src_ptr) \
    asm volatile("cp.async.cg.shared.global [%0], [%1], 16;" :: "r"(dst_u32), "l"(src_ptr))
#define CP_COMMIT() asm volatile("cp.async.commit_group;")
#define CP_WAIT0()  asm volatile("cp.async.wait_group 0;")

#define MMA_F16(d, a, b)                                               \
    asm volatile(                                                      \
        "mma.sync.aligned.m16n8k16.row.col.f32.f16.f16.f32 "           \
        "{%0,%1,%2,%3}, {%4,%5,%6,%7}, {%8,%9}, {%0,%1,%2,%3};\n"      \
        : "+f"((d)[0]), "+f"((d)[1]), "+f"((d)[2]), "+f"((d)[3])       \
        : "r"((a)[0]), "r"((a)[1]), "r"((a)[2]), "r"((a)[3]),          \
          "r"((b)[0]), "r"((b)[1]))

__global__ __launch_bounds__(THREADS, 2)
void ghost_gemm(const float* __restrict__ x, float* __restrict__ out) {
    extern __shared__ uint32_t smem[];
    uint32_t* As = smem;                 // 2 buffers
    uint32_t* Bs = smem + 2 * TILE32;    // 2 buffers

    const int tid = threadIdx.x;
    const int m0 = blockIdx.x * BM;      // M fastest -> W L2 reuse
    const int n0 = blockIdx.y * BN;

    // loader roles
    const int arow = tid & 127, ahalf = tid >> 7;          // x: row, 16-float half
    const float* xsrc = x + (size_t)(m0 + arow) * K_TOTAL + ahalf * 16;
    const int brow = tid & 127, bc = tid >> 7;             // W: row, chunk 0/1 (+2)
    const __half* wsrc = g_W + (size_t)(n0 + brow) * K_TOTAL;

    // warp/fragment coords
    const int warp = tid >> 5, lane = tid & 31;
    const int warp_m = warp & 1;   // 2 warps x 64 rows
    const int warp_n = warp >> 1;  // 4 warps x 32 cols
    const int qid = lane >> 2, tg = lane & 3;

    float acc[4][4][4];
    #pragma unroll
    for (int mt = 0; mt < 4; mt++)
        #pragma unroll
        for (int nt = 0; nt < 4; nt++)
            #pragma unroll
            for (int r = 0; r < 4; r++) acc[mt][nt][r] = 0.0f;

    // ---- prologue: stage 0 ----
    float4 xa = *(const float4*)(xsrc);
    float4 xb = *(const float4*)(xsrc + 4);
    float4 xc = *(const float4*)(xsrc + 8);
    float4 xd = *(const float4*)(xsrc + 12);
    {
        uint32_t bdst = (uint32_t)__cvta_generic_to_shared(&Bs[brow * LD32 + bc * 4]);
        CP16(bdst, wsrc + bc * 8);
        CP16(bdst + 32u, wsrc + (bc + 2) * 8);   // +2 chunks = +8 u32 = +32B
        CP_COMMIT();
    }

    int buf = 0;
    for (int s = 0; s < NS; ++s) {
        // STS x (stage s) into A[buf]
        {
            uint32_t* ad = &As[buf * TILE32 + arow * LD32 + ahalf * 8];
            uint4 p0, p1;
            p0.x = h2_to_u32(__floats2half2_rn(xa.x, xa.y));
            p0.y = h2_to_u32(__floats2half2_rn(xa.z, xa.w));
            p0.z = h2_to_u32(__floats2half2_rn(xb.x, xb.y));
            p0.w = h2_to_u32(__floats2half2_rn(xb.z, xb.w));
            p1.x = h2_to_u32(__floats2half2_rn(xc.x, xc.y));
            p1.y = h2_to_u32(__floats2half2_rn(xc.z, xc.w));
            p1.z = h2_to_u32(__floats2half2_rn(xd.x, xd.y));
            p1.w = h2_to_u32(__floats2half2_rn(xd.z, xd.w));
            *(uint4*)(ad) = p0;
            *(uint4*)(ad + 4) = p1;
        }
        CP_WAIT0();
        __syncthreads();  // A[buf],B[buf] visible; prior MMA on buf^1 done

        // prefetch stage s+1
        if (s + 1 < NS) {
            const float* xs = xsrc + (s + 1) * BK;
            xa = *(const float4*)(xs);
            xb = *(const float4*)(xs + 4);
            xc = *(const float4*)(xs + 8);
            xd = *(const float4*)(xs + 12);
            uint32_t bdst = (uint32_t)__cvta_generic_to_shared(
                &Bs[(buf ^ 1) * TILE32 + brow * LD32 + bc * 4]);
            const __half* ws = wsrc + (s + 1) * BK;
            CP16(bdst, ws + bc * 8);
            CP16(bdst + 32u, ws + (bc + 2) * 8);
            CP_COMMIT();
        }

        // MMA on buf
        {
            const uint32_t* A = &As[buf * TILE32];
            const uint32_t* B = &Bs[buf * TILE32];
            #pragma unroll
            for (int ks = 0; ks < 2; ks++) {
                const int ko = ks * 8 + tg;
                uint32_t afr[4][4], bfr[4][2];
                #pragma unroll
                for (int mt = 0; mt < 4; mt++) {
                    int r = warp_m * 64 + mt * 16 + qid;
                    afr[mt][0] = A[r * LD32 + ko];
                    afr[mt][1] = A[(r + 8) * LD32 + ko];
                    afr[mt][2] = A[r * LD32 + ko + 4];
                    afr[mt][3] = A[(r + 8) * LD32 + ko + 4];
                }
                #pragma unroll
                for (int nt = 0; nt < 4; nt++) {
                    int c = warp_n * 32 + nt * 8 + qid;
                    bfr[nt][0] = B[c * LD32 + ko];
                    bfr[nt][1] = B[c * LD32 + ko + 4];
                }
                #pragma unroll
                for (int mt = 0; mt < 4; mt++)
                    #pragma unroll
                    for (int nt = 0; nt < 4; nt++)
                        MMA_F16(acc[mt][nt], afr[mt], bfr[nt]);
            }
        }
        __syncthreads();  // all warps done with buf before next STS overwrites it
        buf ^= 1;
    }

    // epilogue
    #pragma unroll
    for (int mt = 0; mt < 4; mt++) {
        #pragma unroll
        for (int nt = 0; nt < 4; nt++) {
            int row = m0 + warp_m * 64 + mt * 16 + qid;
            int col = n0 + warp_n * 32 + nt * 8 + tg * 2;
            *(float2*)&out[(size_t)row * N_TOTAL + col] =
                make_float2(acc[mt][nt][0], acc[mt][nt][1]);
            *(float2*)&out[(size_t)(row + 8) * N_TOTAL + col] =
                make_float2(acc[mt][nt][2], acc[mt][nt][3]);
        }
    }
}

extern "C" void kernel_launch(void* const* d_in, const int* in_sizes, int n_in,
                              void* d_out, int out_size) {
    const float* x        = (const float*)d_in[0];
    const int*   base_idx = (const int*)d_in[1];
    const int*   fine_idx = (const int*)d_in[2];
    const float* scale    = (const float*)d_in[3];
    const float* lut      = (const float*)d_in[4];
    float* out = (float*)d_out;

    cudaFuncSetAttribute(ghost_dequant, cudaFuncAttributeMaxDynamicSharedMemorySize,
                         131072);
    cudaFuncSetAttribute(ghost_gemm, cudaFuncAttributeMaxDynamicSharedMemorySize,
                         SMEM_GEMM);

    ghost_dequant<<<148, 1024, 131072>>>(base_idx, fine_idx, scale, lut);
    dim3 grid(M_TOTAL / BM, N_TOTAL / BN);  // (4, 64), M fastest
    ghost_gemm<<<grid, THREADS, SMEM_GEMM>>>(x, out);
}

// round 5
// speedup vs baseline: 3.6390x; 2.1397x over previous
#include <cuda_runtime.h>
#include <cuda_fp16.h>
#include <cstdint>

// GhostLinearTandem, two-pass (tcgen05 unavailable: harness PTX target sm_103):
//  pass 1 (ghost_dequant): W fp16 -> 64MiB scratch (LUT fp16 in smem), x -> fp16.
//  pass 2 (ghost_gemm): fp16 mma.sync m16n8k16, BM=BN=128, BK=64,
//    ldmatrix.x4 fragment loads on SW128-swizzled smem, cp.async 3-stage ring,
//    one barrier per stage, 2 CTAs/SM, grid (4,64) single wave (W L2 reuse).

#define M_TOTAL 512
#define N_TOTAL 8192
#define K_TOTAL 4096

__device__ __align__(16) __half g_W[(size_t)N_TOTAL * K_TOTAL];   // 64 MiB
__device__ __align__(16) __half g_xh[(size_t)M_TOTAL * K_TOTAL];  // 4 MiB

__device__ __forceinline__ uint32_t smem_u32(const void* p) {
    uint32_t a;
    asm("{ .reg .u64 t; cvta.to.shared.u64 t, %1; cvt.u32.u64 %0, t; }"
        : "=r"(a) : "l"(p));
    return a;
}
#define SWZ128(off) ((off) ^ (((off) >> 3) & 0x70))

#define CP16(dst, src) \
    asm volatile("cp.async.cg.shared.global [%0], [%1], 16;" :: "r"(dst), "l"(src))
#define CP_COMMIT() asm volatile("cp.async.commit_group;")
#define CP_WAIT1()  asm volatile("cp.async.wait_group 1;")

#define LDSM_X4(r0, r1, r2, r3, addr)                                     \
    asm volatile("ldmatrix.sync.aligned.m8n8.x4.shared.b16 {%0,%1,%2,%3}, [%4];" \
                 : "=r"(r0), "=r"(r1), "=r"(r2), "=r"(r3) : "r"(addr))

#define MMA_F16(d, a0, a1, a2, a3, b0, b1)                             \
    asm volatile(                                                      \
        "mma.sync.aligned.m16n8k16.row.col.f32.f16.f16.f32 "           \
        "{%0,%1,%2,%3}, {%4,%5,%6,%7}, {%8,%9}, {%0,%1,%2,%3};\n"      \
        : "+f"((d)[0]), "+f"((d)[1]), "+f"((d)[2]), "+f"((d)[3])       \
        : "r"(a0), "r"(a1), "r"(a2), "r"(a3), "r"(b0), "r"(b1))

// ---------------------------------------------------------------- pass 1
__global__ __launch_bounds__(1024)
void ghost_dequant(const int* __restrict__ base_idx,
                   const int* __restrict__ fine_idx,
                   const float* __restrict__ scale,
                   const float* __restrict__ lut,
                   const float* __restrict__ x) {
    extern __shared__ __half lut_s[];  // 65536 fp16 = 128KB
    #pragma unroll 4
    for (int i = threadIdx.x; i < 65536; i += 1024)
        lut_s[i] = __float2half_rn(lut[i]);
    __syncthreads();

    size_t t = (size_t)blockIdx.x * blockDim.x + threadIdx.x;
    size_t stride = (size_t)gridDim.x * blockDim.x;

    // x fp32 -> fp16
    const float4* xp = (const float4*)x;
    for (size_t g = t; g < (size_t)M_TOTAL * K_TOTAL / 8; g += stride) {
        float4 u = xp[2 * g], v = xp[2 * g + 1];
        __half2 h[4] = {__floats2half2_rn(u.x, u.y), __floats2half2_rn(u.z, u.w),
                        __floats2half2_rn(v.x, v.y), __floats2half2_rn(v.z, v.w)};
        *(uint4*)&g_xh[g * 8] = *(uint4*)h;
    }

    const int4* bp = (const int4*)base_idx;
    const int4* fp = (const int4*)fine_idx;
    for (size_t g = t; g < (size_t)N_TOTAL * K_TOTAL / 8; g += stride) {
        int row = (int)(g >> 9);
        float scl = __ldg(&scale[row]);
        int4 b0 = bp[2 * g], b1 = bp[2 * g + 1];
        int4 f0 = fp[2 * g], f1 = fp[2 * g + 1];
        __half2 h[4];
        h[0] = __floats2half2_rn(__half2float(lut_s[(b0.x << 8) + f0.x]) * scl,
                                 __half2float(lut_s[(b0.y << 8) + f0.y]) * scl);
        h[1] = __floats2half2_rn(__half2float(lut_s[(b0.z << 8) + f0.z]) * scl,
                                 __half2float(lut_s[(b0.w << 8) + f0.w]) * scl);
        h[2] = __floats2half2_rn(__half2float(lut_s[(b1.x << 8) + f1.x]) * scl,
                                 __half2float(lut_s[(b1.y << 8) + f1.y]) * scl);
        h[3] = __floats2half2_rn(__half2float(lut_s[(b1.z << 8) + f1.z]) * scl,
                                 __half2float(lut_s[(b1.w << 8) + f1.w]) * scl);
        *(uint4*)&g_W[g * 8] = *(uint4*)h;
    }
}

// ---------------------------------------------------------------- pass 2
#define BM 128
#define BN 128
#define BKH 64                      // halves per stage (128 B per row)
#define NS (K_TOTAL / BKH)          // 64 stages
#define NSLOT 3
#define A_BYTES (BM * 128)          // 16384
#define STAGE_BYTES (2 * A_BYTES)   // A + B = 32768
#define SMEM_GEMM (NSLOT * STAGE_BYTES)  // 98304
#define THREADS 256

__global__ __launch_bounds__(THREADS, 2)
void ghost_gemm(float* __restrict__ out) {
    extern __shared__ char smem[];
    const uint32_t sb = smem_u32(smem);
    const int tid = threadIdx.x;
    const int warp = tid >> 5, lane = tid & 31;
    const int m0 = blockIdx.x * BM;   // M fastest -> W L2 reuse
    const int n0 = blockIdx.y * BN;

    const __half* Ag = g_xh + (size_t)m0 * K_TOTAL;
    const __half* Bg = g_W + (size_t)n0 * K_TOTAL;

    // loader role: 2048 16B chunks/stage; c<1024 -> A, else B; 8 per thread
    const int lrow = tid >> 3;           // 0..31 (A) base; c pattern below
    const int lci = tid & 7;
    (void)lrow; (void)lci;

    auto load_stage = [&](int s, int slot) {
        const int kh = s * BKH;
        #pragma unroll
        for (int i = 0; i < 8; i++) {
            int c = tid + i * THREADS;           // 0..2047
            int cc = c & 1023;
            int row = cc >> 3, ci = cc & 7;
            uint32_t dst = sb + slot * STAGE_BYTES + ((c < 1024) ? 0 : A_BYTES) +
                           SWZ128(row * 128 + ci * 16);
            const __half* src = (c < 1024)
                ? Ag + (size_t)row * K_TOTAL + kh + ci * 8
                : Bg + (size_t)row * K_TOTAL + kh + ci * 8;
            CP16(dst, src);
        }
        CP_COMMIT();
    };

    // warp tiling: 2 warps x 64 M-rows, 4 warps x 32 N-cols
    const int warp_m = warp & 1;
    const int warp_n = warp >> 1;

    // ldmatrix per-lane invariants
    const int a_row0 = warp_m * 64 + ((lane >> 3) & 1) * 8 + (lane & 7);
    const int a_koff = (lane >> 4) * 8;               // halves
    const int b_row0 = warp_n * 32 + ((lane >> 4) & 1) * 8 + (lane & 7);
    const int b_koff = ((lane >> 3) & 1) * 8;

    float acc[4][4][4];
    #pragma unroll
    for (int mt = 0; mt < 4; mt++)
        #pragma unroll
        for (int nt = 0; nt < 4; nt++)
            #pragma unroll
            for (int r = 0; r < 4; r++) acc[mt][nt][r] = 0.0f;

    load_stage(0, 0);
    load_stage(1, 1);

    int slot = 0;
    for (int s = 0; s < NS; ++s) {
        CP_WAIT1();
        __syncthreads();   // stage s resident in all threads' view

        const uint32_t Abase = sb + slot * STAGE_BYTES;
        const uint32_t Bbase = Abase + A_BYTES;

        #pragma unroll
        for (int ks = 0; ks < 4; ks++) {
            const int k0 = ks * 16;  // halves
            uint32_t af[4][4], bf[2][4];
            #pragma unroll
            for (int mt = 0; mt < 4; mt++) {
                uint32_t ad = Abase +
                    SWZ128((a_row0 + mt * 16) * 128 + (k0 + a_koff) * 2);
                LDSM_X4(af[mt][0], af[mt][1], af[mt][2], af[mt][3], ad);
            }
            #pragma unroll
            for (int np = 0; np < 2; np++) {
                uint32_t bd = Bbase +
                    SWZ128((b_row0 + np * 16) * 128 + (k0 + b_koff) * 2);
                LDSM_X4(bf[np][0], bf[np][1], bf[np][2], bf[np][3], bd);
            }
            #pragma unroll
            for (int mt = 0; mt < 4; mt++)
                #pragma unroll
                for (int nt = 0; nt < 4; nt++)
                    MMA_F16(acc[mt][nt],
                            af[mt][0], af[mt][1], af[mt][2], af[mt][3],
                            bf[nt >> 1][(nt & 1) * 2],
                            bf[nt >> 1][(nt & 1) * 2 + 1]);
        }

        if (s + 2 < NS)
            load_stage(s + 2, (slot + 2) % NSLOT);
        else
            CP_COMMIT();   // empty group keeps wait_group accounting exact
        slot = (slot + 1) % NSLOT;
    }

    // epilogue (frag layout: qid=lane>>2 rows, tg=lane&3 col pairs)
    const int qid = lane >> 2, tg = lane & 3;
    #pragma unroll
    for (int mt = 0; mt < 4; mt++) {
        #pragma unroll
        for (int nt = 0; nt < 4; nt++) {
            int row = m0 + warp_m * 64 + mt * 16 + qid;
            int col = n0 + warp_n * 32 + nt * 8 + tg * 2;
            *(float2*)&out[(size_t)row * N_TOTAL + col] =
                make_float2(acc[mt][nt][0], acc[mt][nt][1]);
            *(float2*)&out[(size_t)(row + 8) * N_TOTAL + col] =
                make_float2(acc[mt][nt][2], acc[mt][nt][3]);
        }
    }
}

extern "C" void kernel_launch(void* const* d_in, const int* in_sizes, int n_in,
                              void* d_out, int out_size) {
    const float* x        = (const float*)d_in[0];
    const int*   base_idx = (const int*)d_in[1];
    const int*   fine_idx = (const int*)d_in[2];
    const float* scale    = (const float*)d_in[3];
    const float* lut      = (const float*)d_in[4];
    float* out = (float*)d_out;

    cudaFuncSetAttribute(ghost_dequant, cudaFuncAttributeMaxDynamicSharedMemorySize,
                         131072);
    cudaFuncSetAttribute(ghost_gemm, cudaFuncAttributeMaxDynamicSharedMemorySize,
                         SMEM_GEMM);

    ghost_dequant<<<148, 1024, 131072>>>(base_idx, fine_idx, scale, lut, x);
    dim3 grid(M_TOTAL / BM, N_TOTAL / BN);  // (4, 64), M fastest
    ghost_gemm<<<grid, THREADS, SMEM_GEMM>>>(out);
}

// round 6
// speedup vs baseline: 3.6973x; 1.0160x over previous
#include <cuda_runtime.h>
#include <cuda_fp16.h>
#include <cstdint>

// GhostLinearTandem, two-pass (tcgen05 rejected by harness ptxas target sm_103):
//  pass 1 (ghost_dequant): W fp16 -> 64MiB scratch (LUT fp16 in smem), x -> fp16.
//  pass 2 (ghost_gemm): fp16 mma.sync m16n8k16, BM=BN=128, BK=64,
//    4 warps x (64x64) warp tiles  -> LDSM/MMA ratio 0.25,
//    ldmatrix.x4 on SW128-swizzled smem, cp.async 3-stage ring,
//    one barrier per stage, 2 CTAs/SM, grid (4,64) M-fastest (W L2 reuse).

#define M_TOTAL 512
#define N_TOTAL 8192
#define K_TOTAL 4096

__device__ __align__(16) __half g_W[(size_t)N_TOTAL * K_TOTAL];   // 64 MiB
__device__ __align__(16) __half g_xh[(size_t)M_TOTAL * K_TOTAL];  // 4 MiB

__device__ __forceinline__ uint32_t smem_u32(const void* p) {
    uint32_t a;
    asm("{ .reg .u64 t; cvta.to.shared.u64 t, %1; cvt.u32.u64 %0, t; }"
        : "=r"(a) : "l"(p));
    return a;
}
#define SWZ128(off) ((off) ^ (((off) >> 3) & 0x70))

#define CP16(dst, src) \
    asm volatile("cp.async.cg.shared.global [%0], [%1], 16;" :: "r"(dst), "l"(src))
#define CP_COMMIT() asm volatile("cp.async.commit_group;")
#define CP_WAIT1()  asm volatile("cp.async.wait_group 1;")

#define LDSM_X4(r0, r1, r2, r3, addr)                                     \
    asm volatile("ldmatrix.sync.aligned.m8n8.x4.shared.b16 {%0,%1,%2,%3}, [%4];" \
                 : "=r"(r0), "=r"(r1), "=r"(r2), "=r"(r3) : "r"(addr))

#define MMA_F16(d, a0, a1, a2, a3, b0, b1)                             \
    asm volatile(                                                      \
        "mma.sync.aligned.m16n8k16.row.col.f32.f16.f16.f32 "           \
        "{%0,%1,%2,%3}, {%4,%5,%6,%7}, {%8,%9}, {%0,%1,%2,%3};\n"      \
        : "+f"((d)[0]), "+f"((d)[1]), "+f"((d)[2]), "+f"((d)[3])       \
        : "r"(a0), "r"(a1), "r"(a2), "r"(a3), "r"(b0), "r"(b1))

// ---------------------------------------------------------------- pass 1
__global__ __launch_bounds__(1024)
void ghost_dequant(const int* __restrict__ base_idx,
                   const int* __restrict__ fine_idx,
                   const float* __restrict__ scale,
                   const float* __restrict__ lut,
                   const float* __restrict__ x) {
    extern __shared__ __half lut_s[];  // 65536 fp16 = 128KB
    #pragma unroll 4
    for (int i = threadIdx.x; i < 65536; i += 1024)
        lut_s[i] = __float2half_rn(lut[i]);
    __syncthreads();

    size_t t = (size_t)blockIdx.x * blockDim.x + threadIdx.x;
    size_t stride = (size_t)gridDim.x * blockDim.x;

    // x fp32 -> fp16
    const float4* xp = (const float4*)x;
    for (size_t g = t; g < (size_t)M_TOTAL * K_TOTAL / 8; g += stride) {
        float4 u = xp[2 * g], v = xp[2 * g + 1];
        __half2 h[4] = {__floats2half2_rn(u.x, u.y), __floats2half2_rn(u.z, u.w),
                        __floats2half2_rn(v.x, v.y), __floats2half2_rn(v.z, v.w)};
        *(uint4*)&g_xh[g * 8] = *(uint4*)h;
    }

    const int4* bp = (const int4*)base_idx;
    const int4* fp = (const int4*)fine_idx;
    for (size_t g = t; g < (size_t)N_TOTAL * K_TOTAL / 8; g += stride) {
        int row = (int)(g >> 9);
        float scl = __ldg(&scale[row]);
        int4 b0 = bp[2 * g], b1 = bp[2 * g + 1];
        int4 f0 = fp[2 * g], f1 = fp[2 * g + 1];
        __half2 h[4];
        h[0] = __floats2half2_rn(__half2float(lut_s[(b0.x << 8) + f0.x]) * scl,
                                 __half2float(lut_s[(b0.y << 8) + f0.y]) * scl);
        h[1] = __floats2half2_rn(__half2float(lut_s[(b0.z << 8) + f0.z]) * scl,
                                 __half2float(lut_s[(b0.w << 8) + f0.w]) * scl);
        h[2] = __floats2half2_rn(__half2float(lut_s[(b1.x << 8) + f1.x]) * scl,
                                 __half2float(lut_s[(b1.y << 8) + f1.y]) * scl);
        h[3] = __floats2half2_rn(__half2float(lut_s[(b1.z << 8) + f1.z]) * scl,
                                 __half2float(lut_s[(b1.w << 8) + f1.w]) * scl);
        *(uint4*)&g_W[g * 8] = *(uint4*)h;
    }
}

// ---------------------------------------------------------------- pass 2
#define BM 128
#define BN 128
#define BKH 64                      // halves per stage (128 B per row)
#define NS (K_TOTAL / BKH)          // 64 stages
#define NSLOT 3
#define A_BYTES (BM * 128)          // 16384
#define STAGE_BYTES (2 * A_BYTES)   // A + B = 32768
#define SMEM_GEMM (NSLOT * STAGE_BYTES)  // 98304
#define THREADS 128                 // 4 warps, each 64x64

__global__ __launch_bounds__(THREADS, 2)
void ghost_gemm(float* __restrict__ out) {
    extern __shared__ char smem[];
    const uint32_t sb = smem_u32(smem);
    const int tid = threadIdx.x;
    const int warp = tid >> 5, lane = tid & 31;
    const int m0 = blockIdx.x * BM;   // M fastest -> W L2 reuse
    const int n0 = blockIdx.y * BN;

    const __half* Ag = g_xh + (size_t)m0 * K_TOTAL;
    const __half* Bg = g_W + (size_t)n0 * K_TOTAL;

    // loader role: 2048 16B chunks/stage; c<1024 -> A, else B; 16 per thread
    auto load_stage = [&](int s, int slot) {
        const int kh = s * BKH;
        #pragma unroll
        for (int i = 0; i < 16; i++) {
            int c = tid + i * THREADS;           // 0..2047
            int cc = c & 1023;
            int row = cc >> 3, ci = cc & 7;
            uint32_t dst = sb + slot * STAGE_BYTES + ((c < 1024) ? 0 : A_BYTES) +
                           SWZ128(row * 128 + ci * 16);
            const __half* src = (c < 1024)
                ? Ag + (size_t)row * K_TOTAL + kh + ci * 8
                : Bg + (size_t)row * K_TOTAL + kh + ci * 8;
            CP16(dst, src);
        }
        CP_COMMIT();
    };

    // warp tiling: 2 warps along M x 2 along N, each 64x64
    const int warp_m = warp & 1;
    const int warp_n = warp >> 1;

    // ldmatrix per-lane invariants
    const int a_row0 = warp_m * 64 + ((lane >> 3) & 1) * 8 + (lane & 7);
    const int a_koff = (lane >> 4) * 8;               // halves
    const int b_row0 = warp_n * 64 + ((lane >> 4) & 1) * 8 + (lane & 7);
    const int b_koff = ((lane >> 3) & 1) * 8;

    float acc[4][8][4];
    #pragma unroll
    for (int mt = 0; mt < 4; mt++)
        #pragma unroll
        for (int nt = 0; nt < 8; nt++)
            #pragma unroll
            for (int r = 0; r < 4; r++) acc[mt][nt][r] = 0.0f;

    load_stage(0, 0);
    load_stage(1, 1);

    int slot = 0;
    for (int s = 0; s < NS; ++s) {
        CP_WAIT1();
        __syncthreads();   // stage s resident in all threads' view

        const uint32_t Abase = sb + slot * STAGE_BYTES;
        const uint32_t Bbase = Abase + A_BYTES;

        #pragma unroll
        for (int ks = 0; ks < 4; ks++) {
            const int k0 = ks * 16;  // halves
            uint32_t af[4][4], bf[4][4];
            #pragma unroll
            for (int mt = 0; mt < 4; mt++) {
                uint32_t ad = Abase +
                    SWZ128((a_row0 + mt * 16) * 128 + (k0 + a_koff) * 2);
                LDSM_X4(af[mt][0], af[mt][1], af[mt][2], af[mt][3], ad);
            }
            #pragma unroll
            for (int np = 0; np < 4; np++) {
                uint32_t bd = Bbase +
                    SWZ128((b_row0 + np * 16) * 128 + (k0 + b_koff) * 2);
                LDSM_X4(bf[np][0], bf[np][1], bf[np][2], bf[np][3], bd);
            }
            #pragma unroll
            for (int mt = 0; mt < 4; mt++)
                #pragma unroll
                for (int nt = 0; nt < 8; nt++)
                    MMA_F16(acc[mt][nt],
                            af[mt][0], af[mt][1], af[mt][2], af[mt][3],
                            bf[nt >> 1][(nt & 1) * 2],
                            bf[nt >> 1][(nt & 1) * 2 + 1]);
        }

        if (s + 2 < NS)
            load_stage(s + 2, (slot + 2) % NSLOT);
        else
            CP_COMMIT();   // empty group keeps wait_group accounting exact
        slot = (slot + 1) % NSLOT;
    }

    // epilogue (frag layout: qid=lane>>2 rows, tg=lane&3 col pairs)
    const int qid = lane >> 2, tg = lane & 3;
    #pragma unroll
    for (int mt = 0; mt < 4; mt++) {
        #pragma unroll
        for (int nt = 0; nt < 8; nt++) {
            int row = m0 + warp_m * 64 + mt * 16 + qid;
            int col = n0 + warp_n * 64 + nt * 8 + tg * 2;
            *(float2*)&out[(size_t)row * N_TOTAL + col] =
                make_float2(acc[mt][nt][0], acc[mt][nt][1]);
            *(float2*)&out[(size_t)(row + 8) * N_TOTAL + col] =
                make_float2(acc[mt][nt][2], acc[mt][nt][3]);
        }
    }
}

extern "C" void kernel_launch(void* const* d_in, const int* in_sizes, int n_in,
                              void* d_out, int out_size) {
    const float* x        = (const float*)d_in[0];
    const int*   base_idx = (const int*)d_in[1];
    const int*   fine_idx = (const int*)d_in[2];
    const float* scale    = (const float*)d_in[3];
    const float* lut      = (const float*)d_in[4];
    float* out = (float*)d_out;

    cudaFuncSetAttribute(ghost_dequant, cudaFuncAttributeMaxDynamicSharedMemorySize,
                         131072);
    cudaFuncSetAttribute(ghost_gemm, cudaFuncAttributeMaxDynamicSharedMemorySize,
                         SMEM_GEMM);

    ghost_dequant<<<148, 1024, 131072>>>(base_idx, fine_idx, scale, lut, x);
    dim3 grid(M_TOTAL / BM, N_TOTAL / BN);  // (4, 64), M fastest
    ghost_gemm<<<grid, THREADS, SMEM_GEMM>>>(out);
}